// round 2
// baseline (speedup 1.0000x reference)
#include <cuda_runtime.h>
#include <cuda_bf16.h>
#include <cstdint>

// Problem constants
#define C_IN     256
#define HIDDEN   64
#define CIN2     96     // HIDDEN + HIDDEN/2
#define TPB      256    // threads per block = pixels per block
// smem: W1 [256][64] + W2 [96][256] + b1[64] + b2[256]
#define SW1_FLOATS (C_IN * HIDDEN)        // 16384
#define SW2_FLOATS (CIN2 * C_IN)          // 24576
#define SMEM_FLOATS (SW1_FLOATS + SW2_FLOATS + HIDDEN + C_IN)  // 41280
#define SMEM_BYTES (SMEM_FLOATS * 4)      // 165120

__device__ __forceinline__ unsigned long long fma2(unsigned long long a,
                                                   unsigned long long b,
                                                   unsigned long long c) {
    unsigned long long d;
    asm("fma.rn.f32x2 %0, %1, %2, %3;" : "=l"(d) : "l"(a), "l"(b), "l"(c));
    return d;
}
__device__ __forceinline__ unsigned long long pack2(float x, float y) {
    unsigned long long d;
    asm("mov.b64 %0, {%1, %2};" : "=l"(d) : "f"(x), "f"(y));
    return d;
}
__device__ __forceinline__ float2 unpack2(unsigned long long a) {
    float2 r;
    asm("mov.b64 {%0, %1}, %2;" : "=f"(r.x), "=f"(r.y) : "l"(a));
    return r;
}

// One fused level: y = x@W1+b1 ; z = [y[0:32], y[32:64], relu(y[32:64])] ; o = z@W2+b2
// x: [B, 256, H, W] fp32, out: [B, 256, H, W] fp32. npix = H*W. Each thread = 1 pixel.
__global__ void __launch_bounds__(TPB)
fused_level_kernel(const float* __restrict__ x,
                   const float* __restrict__ W1,   // [256][64]
                   const float* __restrict__ b1,   // [64]
                   const float* __restrict__ W2,   // [96][256]
                   const float* __restrict__ b2,   // [256]
                   float* __restrict__ out,
                   int npix)
{
    extern __shared__ float smem[];
    float* sW1 = smem;                       // 16384
    float* sW2 = smem + SW1_FLOATS;          // 24576
    float* sB1 = smem + SW1_FLOATS + SW2_FLOATS;       // 64
    float* sB2 = sB1 + HIDDEN;                          // 256

    const int tid = threadIdx.x;

    // ---- cooperative weight load (vectorized) ----
    {
        const float4* gW1 = (const float4*)W1;
        float4*       s1  = (float4*)sW1;
        #pragma unroll
        for (int i = 0; i < SW1_FLOATS / 4 / TPB; ++i)          // 16 iters
            s1[tid + i * TPB] = gW1[tid + i * TPB];
        const float4* gW2 = (const float4*)W2;
        float4*       s2  = (float4*)sW2;
        #pragma unroll
        for (int i = 0; i < SW2_FLOATS / 4 / TPB; ++i)          // 24 iters
            s2[tid + i * TPB] = gW2[tid + i * TPB];
        if (tid < HIDDEN) sB1[tid] = b1[tid];
        sB2[tid] = b2[tid];
    }
    __syncthreads();

    // ---- pixel identity ----
    const int g    = blockIdx.x * TPB + tid;      // global pixel (npix % 256 == 0)
    const int img  = g / npix;
    const int p    = g - img * npix;
    const long base = (long)img * C_IN * npix + p;   // x/out index for channel 0

    // ---- phase 1: y[64] = x . W1 + b1 (packed over hidden pairs) ----
    unsigned long long y2[HIDDEN / 2];
    #pragma unroll
    for (int j = 0; j < HIDDEN / 2; ++j)
        y2[j] = pack2(sB1[2 * j], sB1[2 * j + 1]);

    #pragma unroll 4
    for (int c = 0; c < C_IN; ++c) {
        const float xv = x[base + (long)c * npix];
        const unsigned long long xp = pack2(xv, xv);
        const float4* wrow = (const float4*)(sW1 + c * HIDDEN);
        #pragma unroll
        for (int q = 0; q < HIDDEN / 4; ++q) {   // 16 x LDS.128
            float4 w = wrow[q];
            y2[2 * q]     = fma2(xp, pack2(w.x, w.y), y2[2 * q]);
            y2[2 * q + 1] = fma2(xp, pack2(w.z, w.w), y2[2 * q + 1]);
        }
    }

    // unpack y to scalars
    float ys[HIDDEN];
    #pragma unroll
    for (int j = 0; j < HIDDEN / 2; ++j) {
        float2 t = unpack2(y2[j]);
        ys[2 * j]     = t.x;
        ys[2 * j + 1] = t.y;
    }

    // ---- phase 2: o[256] = z . W2 + b2, z = [y0..63, relu(y32..63)] ----
    #pragma unroll 1
    for (int chunk = 0; chunk < C_IN / 32; ++chunk) {   // 8 chunks of 32 out-channels
        const int d0 = chunk * 32;
        unsigned long long o2[16];
        #pragma unroll
        for (int q = 0; q < 16; ++q)
            o2[q] = pack2(sB2[d0 + 2 * q], sB2[d0 + 2 * q + 1]);

        // k = 0..63 : z_k = ys[k]
        #pragma unroll 4
        for (int k = 0; k < HIDDEN; ++k) {
            const unsigned long long zp = pack2(ys[k], ys[k]);
            const float4* wrow = (const float4*)(sW2 + k * C_IN + d0);
            #pragma unroll
            for (int q = 0; q < 8; ++q) {
                float4 w = wrow[q];
                o2[2 * q]     = fma2(zp, pack2(w.x, w.y), o2[2 * q]);
                o2[2 * q + 1] = fma2(zp, pack2(w.z, w.w), o2[2 * q + 1]);
            }
        }
        // k = 64..95 : z_k = relu(ys[k-32])
        #pragma unroll 4
        for (int k = 0; k < HIDDEN / 2; ++k) {
            const float zr = fmaxf(ys[32 + k], 0.0f);
            const unsigned long long zp = pack2(zr, zr);
            const float4* wrow = (const float4*)(sW2 + (HIDDEN + k) * C_IN + d0);
            #pragma unroll
            for (int q = 0; q < 8; ++q) {
                float4 w = wrow[q];
                o2[2 * q]     = fma2(zp, pack2(w.x, w.y), o2[2 * q]);
                o2[2 * q + 1] = fma2(zp, pack2(w.z, w.w), o2[2 * q + 1]);
            }
        }

        // store 32 channels (coalesced across threads)
        #pragma unroll
        for (int q = 0; q < 16; ++q) {
            float2 t = unpack2(o2[q]);
            out[base + (long)(d0 + 2 * q)     * npix] = t.x;
            out[base + (long)(d0 + 2 * q + 1) * npix] = t.y;
        }
    }
}

extern "C" void kernel_launch(void* const* d_in, const int* in_sizes, int n_in,
                              void* d_out, int out_size)
{
    // metadata order: x0, x1, x2, then per level i: W1_i, b1_i, W2_i, b2_i
    const float* x0   = (const float*)d_in[0];
    const float* x1   = (const float*)d_in[1];
    const float* x2   = (const float*)d_in[2];
    const float* W1_0 = (const float*)d_in[3];
    const float* b1_0 = (const float*)d_in[4];
    const float* W2_0 = (const float*)d_in[5];
    const float* b2_0 = (const float*)d_in[6];
    const float* W1_1 = (const float*)d_in[7];
    const float* b1_1 = (const float*)d_in[8];
    const float* W2_1 = (const float*)d_in[9];
    const float* b2_1 = (const float*)d_in[10];
    const float* W1_2 = (const float*)d_in[11];
    const float* b1_2 = (const float*)d_in[12];
    const float* W2_2 = (const float*)d_in[13];
    const float* b2_2 = (const float*)d_in[14];

    float* out = (float*)d_out;
    // output tuple layout: o0 [4,256,128,128] | o1 [4,256,64,64] | o2 [4,256,32,32]
    const long o0_elems = 4L * 256 * 128 * 128;   // 16777216
    const long o1_elems = 4L * 256 * 64 * 64;     //  4194304

    cudaFuncSetAttribute(fused_level_kernel,
                         cudaFuncAttributeMaxDynamicSharedMemorySize, SMEM_BYTES);

    // level 0: 4*16384 px -> 256 blocks
    fused_level_kernel<<<256, TPB, SMEM_BYTES>>>(x0, W1_0, b1_0, W2_0, b2_0,
                                                 out, 128 * 128);
    // level 1: 4*4096 px -> 64 blocks
    fused_level_kernel<<<64, TPB, SMEM_BYTES>>>(x1, W1_1, b1_1, W2_1, b2_1,
                                                out + o0_elems, 64 * 64);
    // level 2: 4*1024 px -> 16 blocks
    fused_level_kernel<<<16, TPB, SMEM_BYTES>>>(x2, W1_2, b1_2, W2_2, b2_2,
                                                out + o0_elems + o1_elems, 32 * 32);
}

// round 3
// speedup vs baseline: 1.7583x; 1.7583x over previous
#include <cuda_runtime.h>
#include <cstdint>

#define C_IN 256
#define HID  64
#define TPB  256
#define NT   128      // pixels per tile
#define YLD  132      // padded y row stride (floats) to break bank conflicts

// dynamic smem layout (floats)
#define SW1_OFF 0                      // [256][64]   16384
#define SW2_OFF 16384                  // [96][256]   24576
#define SY_OFF  40960                  // [64][132]    8448
#define SB2_OFF 49408                  // [256]
#define SB1_OFF 49664                  // [64]
#define SMEM_FLOATS 49728
#define SMEM_BYTES  (SMEM_FLOATS * 4)  // 198912 B

typedef unsigned long long ull;

__device__ __forceinline__ ull fma2(ull a, ull b, ull c) {
    ull d;
    asm("fma.rn.f32x2 %0, %1, %2, %3;" : "=l"(d) : "l"(a), "l"(b), "l"(c));
    return d;
}
__device__ __forceinline__ ull pack2(float x, float y) {
    ull d;
    asm("mov.b64 %0, {%1, %2};" : "=l"(d) : "f"(x), "f"(y));
    return d;
}
__device__ __forceinline__ float2 unpack2(ull a) {
    float2 r;
    asm("mov.b64 {%0, %1}, %2;" : "=f"(r.x), "=f"(r.y) : "l"(a));
    return r;
}

// 16 fma2: acc[mp][n] += a_mp * q_n   (a = M-pair of weights, q = duplicated x/z value)
#define FMA_TILE(ACC, A0, A1, A2, A3, Q0, Q1, Q2, Q3)                 \
    ACC[0]  = fma2(A0, Q0, ACC[0]);  ACC[1]  = fma2(A0, Q1, ACC[1]);  \
    ACC[2]  = fma2(A0, Q2, ACC[2]);  ACC[3]  = fma2(A0, Q3, ACC[3]);  \
    ACC[4]  = fma2(A1, Q0, ACC[4]);  ACC[5]  = fma2(A1, Q1, ACC[5]);  \
    ACC[6]  = fma2(A1, Q2, ACC[6]);  ACC[7]  = fma2(A1, Q3, ACC[7]);  \
    ACC[8]  = fma2(A2, Q0, ACC[8]);  ACC[9]  = fma2(A2, Q1, ACC[9]);  \
    ACC[10] = fma2(A2, Q2, ACC[10]); ACC[11] = fma2(A2, Q3, ACC[11]); \
    ACC[12] = fma2(A3, Q0, ACC[12]); ACC[13] = fma2(A3, Q1, ACC[13]); \
    ACC[14] = fma2(A3, Q2, ACC[14]); ACC[15] = fma2(A3, Q3, ACC[15]);

__global__ void __launch_bounds__(TPB, 1)
fused_all_kernel(const float* __restrict__ x0, const float* __restrict__ x1,
                 const float* __restrict__ x2,
                 const float* __restrict__ W1_0, const float* __restrict__ b1_0,
                 const float* __restrict__ W2_0, const float* __restrict__ b2_0,
                 const float* __restrict__ W1_1, const float* __restrict__ b1_1,
                 const float* __restrict__ W2_1, const float* __restrict__ b2_1,
                 const float* __restrict__ W1_2, const float* __restrict__ b1_2,
                 const float* __restrict__ W2_2, const float* __restrict__ b2_2,
                 float* __restrict__ out)
{
    extern __shared__ float smem[];
    float* sW1 = smem + SW1_OFF;
    float* sW2 = smem + SW2_OFF;
    float* sY  = smem + SY_OFF;
    float* sB2 = smem + SB2_OFF;
    float* sB1 = smem + SB1_OFF;

    // ---- level select (tiles: 512 | 128 | 32) ----
    const int t = blockIdx.x;
    const float *x, *W1, *b1, *W2, *b2;
    float* o;
    int npix, tl;
    if (t < 512) {
        x = x0; W1 = W1_0; b1 = b1_0; W2 = W2_0; b2 = b2_0;
        o = out; npix = 16384; tl = t;
    } else if (t < 640) {
        x = x1; W1 = W1_1; b1 = b1_1; W2 = W2_1; b2 = b2_1;
        o = out + 16777216L; npix = 4096; tl = t - 512;
    } else {
        x = x2; W1 = W1_2; b1 = b1_2; W2 = W2_2; b2 = b2_2;
        o = out + 20971520L; npix = 1024; tl = t - 640;
    }

    const int tid = threadIdx.x;

    // ---- stage weights + biases ----
    {
        const float4* g1 = (const float4*)W1;
        float4*       s1 = (float4*)sW1;
        #pragma unroll
        for (int i = 0; i < 16; ++i) s1[tid + i * TPB] = g1[tid + i * TPB];
        const float4* g2 = (const float4*)W2;
        float4*       s2 = (float4*)sW2;
        #pragma unroll
        for (int i = 0; i < 24; ++i) s2[tid + i * TPB] = g2[tid + i * TPB];
        sB2[tid] = b2[tid];
        if (tid < HID) sB1[tid] = b1[tid];
    }
    __syncthreads();

    // ---- thread tile identity: tm in [0,8) over M-groups, tn in [0,32) over N-groups ----
    const int tm = tid & 7;
    const int tn = tid >> 3;
    const int mb = tm * 8;
    const int tpi  = npix / NT;              // tiles per image
    const int img  = tl / tpi;
    const int p0   = (tl - img * tpi) * NT;
    const long pbase = (long)img * C_IN * npix + p0 + tn * 4;

    // ================= phase 1: Y[64 x 128] = W1^T @ X + b1 =================
    {
        ull acc[16];
        #pragma unroll
        for (int mp = 0; mp < 4; ++mp) {
            const ull bp = pack2(sB1[mb + 2 * mp], sB1[mb + 2 * mp + 1]);
            acc[mp * 4 + 0] = bp; acc[mp * 4 + 1] = bp;
            acc[mp * 4 + 2] = bp; acc[mp * 4 + 3] = bp;
        }
        #pragma unroll 4
        for (int k = 0; k < C_IN; ++k) {
            const float4 xv = *(const float4*)(x + pbase + (long)k * npix);
            const float4* wr = (const float4*)(sW1 + k * HID + mb);
            const float4 wa = wr[0], wb = wr[1];
            const ull a0 = pack2(wa.x, wa.y), a1 = pack2(wa.z, wa.w);
            const ull a2 = pack2(wb.x, wb.y), a3 = pack2(wb.z, wb.w);
            const ull q0 = pack2(xv.x, xv.x), q1 = pack2(xv.y, xv.y);
            const ull q2 = pack2(xv.z, xv.z), q3 = pack2(xv.w, xv.w);
            FMA_TILE(acc, a0, a1, a2, a3, q0, q1, q2, q3)
        }
        // write y tile to smem (padded rows)
        #pragma unroll
        for (int mp = 0; mp < 4; ++mp) {
            #pragma unroll
            for (int n = 0; n < 4; ++n) {
                const float2 tv = unpack2(acc[mp * 4 + n]);
                sY[(mb + 2 * mp)     * YLD + tn * 4 + n] = tv.x;
                sY[(mb + 2 * mp + 1) * YLD + tn * 4 + n] = tv.y;
            }
        }
    }
    __syncthreads();

    // ====== phase 2: O[256 x 128] = W2^T @ [y ; relu(y[32:64])] + b2 ======
    #pragma unroll 1
    for (int mc = 0; mc < 4; ++mc) {
        const int m0 = mc * 64 + mb;
        ull acc[16];
        #pragma unroll
        for (int mp = 0; mp < 4; ++mp) {
            const ull bp = pack2(sB2[m0 + 2 * mp], sB2[m0 + 2 * mp + 1]);
            acc[mp * 4 + 0] = bp; acc[mp * 4 + 1] = bp;
            acc[mp * 4 + 2] = bp; acc[mp * 4 + 3] = bp;
        }

        // k = 0..31 : plain y rows
        #pragma unroll 4
        for (int k = 0; k < 32; ++k) {
            const float4 yv = *(const float4*)(sY + k * YLD + tn * 4);
            const float4* wr = (const float4*)(sW2 + k * C_IN + m0);
            const float4 wa = wr[0], wb = wr[1];
            const ull a0 = pack2(wa.x, wa.y), a1 = pack2(wa.z, wa.w);
            const ull a2 = pack2(wb.x, wb.y), a3 = pack2(wb.z, wb.w);
            const ull q0 = pack2(yv.x, yv.x), q1 = pack2(yv.y, yv.y);
            const ull q2 = pack2(yv.z, yv.z), q3 = pack2(yv.w, yv.w);
            FMA_TILE(acc, a0, a1, a2, a3, q0, q1, q2, q3)
        }

        // j = 0..31 : y row (32+j) used twice — plain for W2 row (32+j),
        // relu'd for W2 row (64+j). One LDS of y serves 32 fma2.
        #pragma unroll 2
        for (int j = 0; j < 32; ++j) {
            const float4 yv = *(const float4*)(sY + (32 + j) * YLD + tn * 4);
            const ull q0 = pack2(yv.x, yv.x), q1 = pack2(yv.y, yv.y);
            const ull q2 = pack2(yv.z, yv.z), q3 = pack2(yv.w, yv.w);
            {
                const float4* wr = (const float4*)(sW2 + (32 + j) * C_IN + m0);
                const float4 wa = wr[0], wb = wr[1];
                const ull a0 = pack2(wa.x, wa.y), a1 = pack2(wa.z, wa.w);
                const ull a2 = pack2(wb.x, wb.y), a3 = pack2(wb.z, wb.w);
                FMA_TILE(acc, a0, a1, a2, a3, q0, q1, q2, q3)
            }
            const float r0 = fmaxf(yv.x, 0.f), r1 = fmaxf(yv.y, 0.f);
            const float r2 = fmaxf(yv.z, 0.f), r3 = fmaxf(yv.w, 0.f);
            const ull p0r = pack2(r0, r0), p1r = pack2(r1, r1);
            const ull p2r = pack2(r2, r2), p3r = pack2(r3, r3);
            {
                const float4* wr = (const float4*)(sW2 + (64 + j) * C_IN + m0);
                const float4 wa = wr[0], wb = wr[1];
                const ull a0 = pack2(wa.x, wa.y), a1 = pack2(wa.z, wa.w);
                const ull a2 = pack2(wb.x, wb.y), a3 = pack2(wb.z, wb.w);
                FMA_TILE(acc, a0, a1, a2, a3, p0r, p1r, p2r, p3r)
            }
        }

        // store 8 output rows x 4 pixels (vectorized)
        #pragma unroll
        for (int mp = 0; mp < 4; ++mp) {
            const float2 t0 = unpack2(acc[mp * 4 + 0]);
            const float2 t1 = unpack2(acc[mp * 4 + 1]);
            const float2 t2 = unpack2(acc[mp * 4 + 2]);
            const float2 t3 = unpack2(acc[mp * 4 + 3]);
            const float4 lo = make_float4(t0.x, t1.x, t2.x, t3.x);
            const float4 hi = make_float4(t0.y, t1.y, t2.y, t3.y);
            *(float4*)(o + pbase + (long)(m0 + 2 * mp)     * npix) = lo;
            *(float4*)(o + pbase + (long)(m0 + 2 * mp + 1) * npix) = hi;
        }
    }
}

extern "C" void kernel_launch(void* const* d_in, const int* in_sizes, int n_in,
                              void* d_out, int out_size)
{
    const float* x0   = (const float*)d_in[0];
    const float* x1   = (const float*)d_in[1];
    const float* x2   = (const float*)d_in[2];
    const float* W1_0 = (const float*)d_in[3];
    const float* b1_0 = (const float*)d_in[4];
    const float* W2_0 = (const float*)d_in[5];
    const float* b2_0 = (const float*)d_in[6];
    const float* W1_1 = (const float*)d_in[7];
    const float* b1_1 = (const float*)d_in[8];
    const float* W2_1 = (const float*)d_in[9];
    const float* b2_1 = (const float*)d_in[10];
    const float* W1_2 = (const float*)d_in[11];
    const float* b1_2 = (const float*)d_in[12];
    const float* W2_2 = (const float*)d_in[13];
    const float* b2_2 = (const float*)d_in[14];

    cudaFuncSetAttribute(fused_all_kernel,
                         cudaFuncAttributeMaxDynamicSharedMemorySize, SMEM_BYTES);

    // 672 tiles of 128 pixels: 512 (level0) + 128 (level1) + 32 (level2)
    fused_all_kernel<<<672, TPB, SMEM_BYTES>>>(
        x0, x1, x2,
        W1_0, b1_0, W2_0, b2_0,
        W1_1, b1_1, W2_1, b2_1,
        W1_2, b1_2, W2_2, b2_2,
        (float*)d_out);
}

// round 4
// speedup vs baseline: 1.8344x; 1.0433x over previous
#include <cuda_runtime.h>
#include <cstdint>

#define C_IN 256
#define HID  64
#define TPB  256
#define NT   128      // pixels per tile
#define YLD  132      // padded y row stride (floats)

// dynamic smem layout (floats)
#define SW1_OFF 0                      // [256][64]   16384
#define SW2_OFF 16384                  // [96][256]   24576
#define SY_OFF  40960                  // [64][132]    8448
#define SB2_OFF 49408                  // [256]
#define SB1_OFF 49664                  // [64]
#define SMEM_FLOATS 49728
#define SMEM_BYTES  (SMEM_FLOATS * 4)  // 198912 B

typedef unsigned long long ull;

__device__ __forceinline__ ull fma2(ull a, ull b, ull c) {
    ull d;
    asm("fma.rn.f32x2 %0, %1, %2, %3;" : "=l"(d) : "l"(a), "l"(b), "l"(c));
    return d;
}
__device__ __forceinline__ ull pack2(float x, float y) {
    ull d;
    asm("mov.b64 %0, {%1, %2};" : "=l"(d) : "f"(x), "f"(y));
    return d;
}
__device__ __forceinline__ float2 unpack2(ull a) {
    float2 r;
    asm("mov.b64 {%0, %1}, %2;" : "=f"(r.x), "=f"(r.y) : "l"(a));
    return r;
}

__global__ void __launch_bounds__(TPB, 1)
fused_all_kernel(const float* __restrict__ x0, const float* __restrict__ x1,
                 const float* __restrict__ x2,
                 const float* __restrict__ W1_0, const float* __restrict__ b1_0,
                 const float* __restrict__ W2_0, const float* __restrict__ b2_0,
                 const float* __restrict__ W1_1, const float* __restrict__ b1_1,
                 const float* __restrict__ W2_1, const float* __restrict__ b2_1,
                 const float* __restrict__ W1_2, const float* __restrict__ b1_2,
                 const float* __restrict__ W2_2, const float* __restrict__ b2_2,
                 float* __restrict__ out)
{
    extern __shared__ float smem[];
    float* sW1 = smem + SW1_OFF;
    float* sW2 = smem + SW2_OFF;
    float* sY  = smem + SY_OFF;
    float* sB2 = smem + SB2_OFF;
    float* sB1 = smem + SB1_OFF;

    // ---- level select (tiles: 512 | 128 | 32) ----
    const int t = blockIdx.x;
    const float *x, *W1, *b1, *W2, *b2;
    float* o;
    int npix, tl;
    if (t < 512) {
        x = x0; W1 = W1_0; b1 = b1_0; W2 = W2_0; b2 = b2_0;
        o = out; npix = 16384; tl = t;
    } else if (t < 640) {
        x = x1; W1 = W1_1; b1 = b1_1; W2 = W2_1; b2 = b2_1;
        o = out + 16777216L; npix = 4096; tl = t - 512;
    } else {
        x = x2; W1 = W1_2; b1 = b1_2; W2 = W2_2; b2 = b2_2;
        o = out + 20971520L; npix = 1024; tl = t - 640;
    }

    const int tid = threadIdx.x;

    // ---- stage weights + biases ----
    {
        const float4* g1 = (const float4*)W1;
        float4*       s1 = (float4*)sW1;
        #pragma unroll
        for (int i = 0; i < 16; ++i) s1[tid + i * TPB] = g1[tid + i * TPB];
        const float4* g2 = (const float4*)W2;
        float4*       s2 = (float4*)sW2;
        #pragma unroll
        for (int i = 0; i < 24; ++i) s2[tid + i * TPB] = g2[tid + i * TPB];
        sB2[tid] = b2[tid];
        if (tid < HID) sB1[tid] = b1[tid];
    }
    __syncthreads();

    const int tpi  = npix / NT;              // tiles per image
    const int img  = tl / tpi;
    const int p0   = (tl - img * tpi) * NT;
    const long ibase = (long)img * C_IN * npix + p0;

    // ================= phase 1: Y[64 x 128] = W1^T @ X + b1 =================
    // thread tile: 8 M x 4 N.  ptm in [0,8), ptn in [0,32)
    {
        const int ptm = tid & 7;
        const int ptn = tid >> 3;
        const int mb  = ptm * 8;
        const long pb = ibase + ptn * 4;

        ull acc[16];
        #pragma unroll
        for (int mp = 0; mp < 4; ++mp) {
            const ull bp = pack2(sB1[mb + 2 * mp], sB1[mb + 2 * mp + 1]);
            acc[mp * 4 + 0] = bp; acc[mp * 4 + 1] = bp;
            acc[mp * 4 + 2] = bp; acc[mp * 4 + 3] = bp;
        }
        #pragma unroll 4
        for (int k = 0; k < C_IN; ++k) {
            const float4 xv = *(const float4*)(x + pb + (long)k * npix);
            const float4* wr = (const float4*)(sW1 + k * HID + mb);
            const float4 wa = wr[0], wb = wr[1];
            const ull a0 = pack2(wa.x, wa.y), a1 = pack2(wa.z, wa.w);
            const ull a2 = pack2(wb.x, wb.y), a3 = pack2(wb.z, wb.w);
            const ull q0 = pack2(xv.x, xv.x), q1 = pack2(xv.y, xv.y);
            const ull q2 = pack2(xv.z, xv.z), q3 = pack2(xv.w, xv.w);
            #pragma unroll
            for (int mp = 0; mp < 4; ++mp) {
                const ull a = (mp == 0) ? a0 : (mp == 1) ? a1 : (mp == 2) ? a2 : a3;
                acc[mp * 4 + 0] = fma2(a, q0, acc[mp * 4 + 0]);
                acc[mp * 4 + 1] = fma2(a, q1, acc[mp * 4 + 1]);
                acc[mp * 4 + 2] = fma2(a, q2, acc[mp * 4 + 2]);
                acc[mp * 4 + 3] = fma2(a, q3, acc[mp * 4 + 3]);
            }
        }
        #pragma unroll
        for (int mp = 0; mp < 4; ++mp) {
            #pragma unroll
            for (int n = 0; n < 4; ++n) {
                const float2 tv = unpack2(acc[mp * 4 + n]);
                sY[(mb + 2 * mp)     * YLD + ptn * 4 + n] = tv.x;
                sY[(mb + 2 * mp + 1) * YLD + ptn * 4 + n] = tv.y;
            }
        }
    }
    __syncthreads();

    // ====== phase 2: O[256 x 128] = W2^T @ [y ; relu(y[32:64])] + b2 ======
    // thread tile: 16 M x 8 N in ONE pass.  tm in [0,16), tn in [0,16)
    {
        const int tm = tid & 15;
        const int tn = tid >> 4;
        const int m0 = tm * 16;
        const int px = tn * 8;
        const long pb = ibase + px;

        ull acc[64];                        // acc[mp*8 + n], mp=0..7 (M-pairs), n=0..7
        #pragma unroll
        for (int mp = 0; mp < 8; ++mp) {
            const ull bp = pack2(sB2[m0 + 2 * mp], sB2[m0 + 2 * mp + 1]);
            #pragma unroll
            for (int n = 0; n < 8; ++n) acc[mp * 8 + n] = bp;
        }

        // ---- k = 0..31 : plain y rows ----
        #pragma unroll 1
        for (int k = 0; k < 32; ++k) {
            const float4 ya = *(const float4*)(sY + k * YLD + px);
            const float4 yb = *(const float4*)(sY + k * YLD + px + 4);
            ull q[8];
            q[0] = pack2(ya.x, ya.x); q[1] = pack2(ya.y, ya.y);
            q[2] = pack2(ya.z, ya.z); q[3] = pack2(ya.w, ya.w);
            q[4] = pack2(yb.x, yb.x); q[5] = pack2(yb.y, yb.y);
            q[6] = pack2(yb.z, yb.z); q[7] = pack2(yb.w, yb.w);
            const float4* wr = (const float4*)(sW2 + k * C_IN + m0);
            #pragma unroll
            for (int h = 0; h < 4; ++h) {
                const float4 w = wr[h];
                const ull aLo = pack2(w.x, w.y), aHi = pack2(w.z, w.w);
                #pragma unroll
                for (int n = 0; n < 8; ++n) {
                    acc[(2 * h) * 8 + n]     = fma2(aLo, q[n], acc[(2 * h) * 8 + n]);
                    acc[(2 * h + 1) * 8 + n] = fma2(aHi, q[n], acc[(2 * h + 1) * 8 + n]);
                }
            }
        }

        // ---- j = 0..31 : y row (32+j) used plain (W2 row 32+j) and relu'd (W2 row 64+j) ----
        #pragma unroll 1
        for (int j = 0; j < 32; ++j) {
            const float4 ya = *(const float4*)(sY + (32 + j) * YLD + px);
            const float4 yb = *(const float4*)(sY + (32 + j) * YLD + px + 4);
            ull q[8];
            q[0] = pack2(ya.x, ya.x); q[1] = pack2(ya.y, ya.y);
            q[2] = pack2(ya.z, ya.z); q[3] = pack2(ya.w, ya.w);
            q[4] = pack2(yb.x, yb.x); q[5] = pack2(yb.y, yb.y);
            q[6] = pack2(yb.z, yb.z); q[7] = pack2(yb.w, yb.w);
            {
                const float4* wr = (const float4*)(sW2 + (32 + j) * C_IN + m0);
                #pragma unroll
                for (int h = 0; h < 4; ++h) {
                    const float4 w = wr[h];
                    const ull aLo = pack2(w.x, w.y), aHi = pack2(w.z, w.w);
                    #pragma unroll
                    for (int n = 0; n < 8; ++n) {
                        acc[(2 * h) * 8 + n]     = fma2(aLo, q[n], acc[(2 * h) * 8 + n]);
                        acc[(2 * h + 1) * 8 + n] = fma2(aHi, q[n], acc[(2 * h + 1) * 8 + n]);
                    }
                }
            }
            ull qr[8];
            qr[0] = pack2(fmaxf(ya.x, 0.f), fmaxf(ya.x, 0.f));
            qr[1] = pack2(fmaxf(ya.y, 0.f), fmaxf(ya.y, 0.f));
            qr[2] = pack2(fmaxf(ya.z, 0.f), fmaxf(ya.z, 0.f));
            qr[3] = pack2(fmaxf(ya.w, 0.f), fmaxf(ya.w, 0.f));
            qr[4] = pack2(fmaxf(yb.x, 0.f), fmaxf(yb.x, 0.f));
            qr[5] = pack2(fmaxf(yb.y, 0.f), fmaxf(yb.y, 0.f));
            qr[6] = pack2(fmaxf(yb.z, 0.f), fmaxf(yb.z, 0.f));
            qr[7] = pack2(fmaxf(yb.w, 0.f), fmaxf(yb.w, 0.f));
            {
                const float4* wr = (const float4*)(sW2 + (64 + j) * C_IN + m0);
                #pragma unroll
                for (int h = 0; h < 4; ++h) {
                    const float4 w = wr[h];
                    const ull aLo = pack2(w.x, w.y), aHi = pack2(w.z, w.w);
                    #pragma unroll
                    for (int n = 0; n < 8; ++n) {
                        acc[(2 * h) * 8 + n]     = fma2(aLo, qr[n], acc[(2 * h) * 8 + n]);
                        acc[(2 * h + 1) * 8 + n] = fma2(aHi, qr[n], acc[(2 * h + 1) * 8 + n]);
                    }
                }
            }
        }

        // ---- store 16 rows x 8 pixels ----
        #pragma unroll
        for (int mp = 0; mp < 8; ++mp) {
            float2 v[8];
            #pragma unroll
            for (int n = 0; n < 8; ++n) v[n] = unpack2(acc[mp * 8 + n]);
            float* r0 = o + pb + (long)(m0 + 2 * mp) * npix;
            float* r1 = o + pb + (long)(m0 + 2 * mp + 1) * npix;
            *(float4*)(r0)     = make_float4(v[0].x, v[1].x, v[2].x, v[3].x);
            *(float4*)(r0 + 4) = make_float4(v[4].x, v[5].x, v[6].x, v[7].x);
            *(float4*)(r1)     = make_float4(v[0].y, v[1].y, v[2].y, v[3].y);
            *(float4*)(r1 + 4) = make_float4(v[4].y, v[5].y, v[6].y, v[7].y);
        }
    }
}

extern "C" void kernel_launch(void* const* d_in, const int* in_sizes, int n_in,
                              void* d_out, int out_size)
{
    const float* x0   = (const float*)d_in[0];
    const float* x1   = (const float*)d_in[1];
    const float* x2   = (const float*)d_in[2];
    const float* W1_0 = (const float*)d_in[3];
    const float* b1_0 = (const float*)d_in[4];
    const float* W2_0 = (const float*)d_in[5];
    const float* b2_0 = (const float*)d_in[6];
    const float* W1_1 = (const float*)d_in[7];
    const float* b1_1 = (const float*)d_in[8];
    const float* W2_1 = (const float*)d_in[9];
    const float* b2_1 = (const float*)d_in[10];
    const float* W1_2 = (const float*)d_in[11];
    const float* b1_2 = (const float*)d_in[12];
    const float* W2_2 = (const float*)d_in[13];
    const float* b2_2 = (const float*)d_in[14];

    cudaFuncSetAttribute(fused_all_kernel,
                         cudaFuncAttributeMaxDynamicSharedMemorySize, SMEM_BYTES);

    // 672 tiles of 128 pixels: 512 (level0) + 128 (level1) + 32 (level2)
    fused_all_kernel<<<672, TPB, SMEM_BYTES>>>(
        x0, x1, x2,
        W1_0, b1_0, W2_0, b2_0,
        W1_1, b1_1, W2_1, b2_1,
        W1_2, b1_2, W2_2, b2_2,
        (float*)d_out);
}